// round 13
// baseline (speedup 1.0000x reference)
#include <cuda_runtime.h>
#include <cuda_bf16.h>
#include <math.h>
#include <stdint.h>

#define NLEV 16
#define TMASK ((1u << 19) - 1u)
#define PR1 2654435761u
#define PR2 805459861u
#define PR3 3674653429u
#define NMAX 2097152

// interleaved feature scratch: plane c in [0,32), point i: g_feat2[c*NMAX+i] = {hi_word, lo_word}
__device__ uint2 g_feat2[32ull * NMAX];
// combined per-level table: (static.xy, time-fused-dynamic.zw) = 16 levels x 512K float4 = 128 MB
__device__ float4 g_tbl_comb[(size_t)NLEV << 19];
// packed coordinates (x0,x1,x2,unused): 32 MB
__device__ float4 g_x4[NMAX];

struct ResParams { int r[NLEV]; };

// ---------------- helpers ----------------
__device__ __forceinline__ void mma16816(float d[4], const uint32_t a[4], uint32_t b0, uint32_t b1) {
    asm volatile("mma.sync.aligned.m16n8k16.row.col.f32.bf16.bf16.f32 "
        "{%0,%1,%2,%3}, {%4,%5,%6,%7}, {%8,%9}, {%0,%1,%2,%3};"
        : "+f"(d[0]), "+f"(d[1]), "+f"(d[2]), "+f"(d[3])
        : "r"(a[0]), "r"(a[1]), "r"(a[2]), "r"(a[3]), "r"(b0), "r"(b1));
}

// fast hi/lo bf16x2 split: 1 cvt + shift/mask reconstruct + 2 fsub + 1 cvt
__device__ __forceinline__ void split2(float v0, float v1, uint32_t& hi, uint32_t& lo) {
    uint32_t h;
    asm("cvt.rn.bf16x2.f32 %0, %1, %2;" : "=r"(h) : "f"(v1), "f"(v0));
    float h0 = __uint_as_float(h << 16);
    float h1 = __uint_as_float(h & 0xFFFF0000u);
    float l0 = v0 - h0, l1 = v1 - h1;
    uint32_t l;
    asm("cvt.rn.bf16x2.f32 %0, %1, %2;" : "=r"(l) : "f"(l1), "f"(l0));
    hi = h; lo = l;
}

// reconstruct fp32 feature from interleaved hi/lo words (idx 0 = low half, 1 = high half)
__device__ __forceinline__ float bf2sum(uint32_t hi, uint32_t lo, int idx) {
    uint32_t hb = idx == 0 ? (hi << 16) : (hi & 0xFFFF0000u);
    uint32_t lb = idx == 0 ? (lo << 16) : (lo & 0xFFFF0000u);
    return __uint_as_float(hb) + __uint_as_float(lb);
}

// elementwise lerps: a + f*(b-a)
__device__ __forceinline__ float2 lerp2(float2 a, float2 b, float f) {
    float2 r;
    r.x = fmaf(f, b.x - a.x, a.x);
    r.y = fmaf(f, b.y - a.y, a.y);
    return r;
}
__device__ __forceinline__ float4 lerp4(float4 a, float4 b, float f) {
    float4 r;
    r.x = fmaf(f, b.x - a.x, a.x);
    r.y = fmaf(f, b.y - a.y, a.y);
    r.z = fmaf(f, b.z - a.z, a.z);
    r.w = fmaf(f, b.w - a.w, a.w);
    return r;
}

// ================= kernel X: pack coordinates into float4 =================
__global__ void __launch_bounds__(256)
pack_x_kernel(const float* __restrict__ x, int N) {
    const int i = blockIdx.x * 256 + threadIdx.x;
    if (i >= N) return;
    g_x4[i] = make_float4(x[3 * i], x[3 * i + 1], x[3 * i + 2], 0.f);
}

// ================= kernel P: build combined table =================
__global__ void __launch_bounds__(256)
build_comb_kernel(const float* __restrict__ tptr,
                  const float* __restrict__ tbl_s,
                  const float* __restrict__ tbl_d, ResParams rp) {
    const int l = blockIdx.y;
    const unsigned j = blockIdx.x * 256 + threadIdx.x;
    const float tv = __ldg(tptr);
    const float p3 = tv * (float)rp.r[l];
    const float g3 = floorf(p3);
    const float f3 = p3 - g3;
    const unsigned i3 = (unsigned)(int)g3;
    const unsigned hw0 = (i3 * PR3) & TMASK;
    const unsigned hw1 = ((i3 + 1u) * PR3) & TMASK;
    const float2* ts = (const float2*)tbl_s + ((size_t)l << 19);
    const float2* td = (const float2*)tbl_d + ((size_t)l << 19);
    float2 s = __ldg(ts + j);
    float2 a = __ldg(td + (j ^ hw0));
    float2 b = __ldg(td + (j ^ hw1));
    float2 d = lerp2(a, b, f3);
    g_tbl_comb[((size_t)l << 19) + j] = make_float4(s.x, s.y, d.x, d.y);
}

// ================= kernel A: level-parallel encode on the combined table =================
__global__ void __launch_bounds__(256)
encode_kernel(int N, ResParams rp) {
    const int i = blockIdx.x * 256 + threadIdx.x;
    if (i >= N) return;
    const int l = blockIdx.y;
    const float4* tb = g_tbl_comb + ((size_t)l << 19);

    const float4 xi = __ldg(&g_x4[i]);
    const float fr = (float)rp.r[l];
    float p0 = xi.x * fr, p1 = xi.y * fr, p2 = xi.z * fr;
    float g0 = floorf(p0), g1 = floorf(p1), g2 = floorf(p2);
    float f0 = p0 - g0, f1 = p1 - g1, f2 = p2 - g2;
    unsigned i0 = (unsigned)(int)g0, i1 = (unsigned)(int)g1, i2 = (unsigned)(int)g2;
    unsigned hy0 = i1 * PR1, hy1 = hy0 + PR1;
    unsigned hz0 = i2 * PR2, hz1 = hz0 + PR2;
    unsigned hyz[4] = { hy0 ^ hz0, hy0 ^ hz1, hy1 ^ hz0, hy1 ^ hz1 };
    unsigned i0b = i0 + 1u;

    float4 vlo[4], vhi[4];
#pragma unroll
    for (int j = 0; j < 4; j++) {
        vlo[j] = __ldg(tb + ((i0  ^ hyz[j]) & TMASK));
        vhi[j] = __ldg(tb + ((i0b ^ hyz[j]) & TMASK));
    }
    float4 u0 = lerp4(vlo[0], vhi[0], f0);
    float4 u1 = lerp4(vlo[1], vhi[1], f0);
    float4 u2 = lerp4(vlo[2], vhi[2], f0);
    float4 u3 = lerp4(vlo[3], vhi[3], f0);
    float4 s0 = lerp4(u0, u2, f1);
    float4 s1 = lerp4(u1, u3, f1);
    float4 r  = lerp4(s0, s1, f2);

    uint32_t hs, ls, hd, ld;
    split2(r.x, r.y, hs, ls);
    split2(r.z, r.w, hd, ld);
    __stcs(&g_feat2[(size_t)l * NMAX + i], make_uint2(hs, ls));
    __stcs(&g_feat2[(size_t)(16 + l) * NMAX + i], make_uint2(hd, ld));
}

// ================= kernel B: 5-layer MLP via HMMA (mt-fused: one B load feeds 6 MMAs) ==========
#define BTPB 256
#define BWARP 8
#define W22_OFF 81920
#define BSMEM (81920 + 256)

__global__ void __launch_bounds__(BTPB, 1)
mlp_kernel(const float* __restrict__ w10, const float* __restrict__ w11,
           const float* __restrict__ w12, const float* __restrict__ w20,
           const float* __restrict__ w21, const float* __restrict__ w22,
           const float* __restrict__ alphap,
           float* __restrict__ out, int N) {
    extern __shared__ char sm[];
    const int tid = threadIdx.x;
    const int wid = tid >> 5;
    const int lane = tid & 31;
    const int gq = lane >> 2;   // quad row 0..7
    const int cq = lane & 3;    // quad col 0..3

    // ---- stage weight fragments (interleaved hi/lo per lane: one LDS.128 per tile) ----
    {
        const float* Ws[5] = { w10, w11, w12, w20, w21 };
#pragma unroll 1
        for (int g = wid; g < 320; g += BWARP) {
            int layer = g >> 6;
            int rem = g & 63;
            int tile = rem >> 1;          // kt*8 + nt
            int j = rem & 1;              // b-register index
            int kt = tile >> 3;
            int k0 = kt * 16 + cq * 2 + j * 8;
            int n = (tile & 7) * 8 + gq;
            const float* W = Ws[layer];
            float v0 = __ldg(W + k0 * 64 + n);
            float v1 = __ldg(W + (k0 + 1) * 64 + n);
            uint32_t hi, lo;
            split2(v0, v1, hi, lo);
            char* base = sm + layer * 16384 + tile * 512 + lane * 16 + j * 4;
            *reinterpret_cast<uint32_t*>(base) = hi;        // bh.j
            *reinterpret_cast<uint32_t*>(base + 8) = lo;    // bl.j
        }
        if (tid < 64) ((float*)(sm + W22_OFF))[tid] = w22[tid];
    }
    __syncthreads();

    const float alpha = __ldg(alphap);
    const float beta = 1.f - alpha;

    const int base_row = blockIdx.x * BTPB + wid * 32;   // mt adds 16
    uint32_t ahi[2][16], alo[2][16];

#pragma unroll
    for (int layer = 0; layer < 5; layer++) {
        float d[2][8][4];
#pragma unroll
        for (int mt = 0; mt < 2; mt++)
#pragma unroll
            for (int nt = 0; nt < 8; nt++)
#pragma unroll
                for (int q = 0; q < 4; q++) d[mt][nt][q] = 0.f;

        const char* wl = sm + layer * 16384;

#pragma unroll
        for (int kt = 0; kt < 4; kt++) {
            uint32_t Ah[2][4], Al[2][4];
            if (layer == 0) {
#pragma unroll
                for (int mt = 0; mt < 2; mt++) {
                    size_t p0 = (size_t)(kt * 8 + cq) * NMAX + base_row + mt * 16 + gq;
                    uint2 a0 = __ldcs(&g_feat2[p0]);
                    uint2 a1 = __ldcs(&g_feat2[p0 + 8]);
                    uint2 a2 = __ldcs(&g_feat2[p0 + 4ull * NMAX]);
                    uint2 a3 = __ldcs(&g_feat2[p0 + 4ull * NMAX + 8]);
                    Ah[mt][0] = a0.x; Al[mt][0] = a0.y;
                    Ah[mt][1] = a1.x; Al[mt][1] = a1.y;
                    Ah[mt][2] = a2.x; Al[mt][2] = a2.y;
                    Ah[mt][3] = a3.x; Al[mt][3] = a3.y;
                }
            } else {
#pragma unroll
                for (int mt = 0; mt < 2; mt++)
#pragma unroll
                    for (int q = 0; q < 4; q++) {
                        Ah[mt][q] = ahi[mt][kt * 4 + q];
                        Al[mt][q] = alo[mt][kt * 4 + q];
                    }
            }
#pragma unroll
            for (int nt = 0; nt < 8; nt++) {
                uint4 w = *reinterpret_cast<const uint4*>(wl + (kt * 8 + nt) * 512 + lane * 16);
#pragma unroll
                for (int mt = 0; mt < 2; mt++) {
                    mma16816(d[mt][nt], Ah[mt], w.x, w.y);
                    mma16816(d[mt][nt], Ah[mt], w.z, w.w);
                    mma16816(d[mt][nt], Al[mt], w.x, w.y);
                }
            }
        }

        if (layer < 4) {
#pragma unroll
            for (int mt = 0; mt < 2; mt++) {
#pragma unroll
                for (int nt = 0; nt < 8; nt++) {
#pragma unroll
                    for (int q = 0; q < 4; q++) d[mt][nt][q] = fmaxf(d[mt][nt][q], 0.f);
                    if (layer == 2) {
                        size_t pw = (size_t)(nt * 4 + cq) * NMAX + base_row + mt * 16 + gq;
                        uint2 fa = __ldcs(&g_feat2[pw]);
                        uint2 fb = __ldcs(&g_feat2[pw + 8]);
                        d[mt][nt][0] = d[mt][nt][0] * alpha + beta * bf2sum(fa.x, fa.y, 0);
                        d[mt][nt][1] = d[mt][nt][1] * alpha + beta * bf2sum(fa.x, fa.y, 1);
                        d[mt][nt][2] = d[mt][nt][2] * alpha + beta * bf2sum(fb.x, fb.y, 0);
                        d[mt][nt][3] = d[mt][nt][3] * alpha + beta * bf2sum(fb.x, fb.y, 1);
                    }
                }
#pragma unroll
                for (int kt = 0; kt < 4; kt++) {
                    split2(d[mt][2 * kt][0],     d[mt][2 * kt][1],     ahi[mt][kt * 4 + 0], alo[mt][kt * 4 + 0]);
                    split2(d[mt][2 * kt][2],     d[mt][2 * kt][3],     ahi[mt][kt * 4 + 1], alo[mt][kt * 4 + 1]);
                    split2(d[mt][2 * kt + 1][0], d[mt][2 * kt + 1][1], ahi[mt][kt * 4 + 2], alo[mt][kt * 4 + 2]);
                    split2(d[mt][2 * kt + 1][2], d[mt][2 * kt + 1][3], ahi[mt][kt * 4 + 3], alo[mt][kt * 4 + 3]);
                }
            }
        } else {
#pragma unroll
            for (int mt = 0; mt < 2; mt++) {
                float s0 = 0.f, s1 = 0.f;
#pragma unroll
                for (int nt = 0; nt < 8; nt++) {
                    float2 wv = *reinterpret_cast<const float2*>(sm + W22_OFF + nt * 32 + cq * 8);
                    s0 = fmaf(fmaxf(d[mt][nt][0], 0.f), wv.x, s0);
                    s0 = fmaf(fmaxf(d[mt][nt][1], 0.f), wv.y, s0);
                    s1 = fmaf(fmaxf(d[mt][nt][2], 0.f), wv.x, s1);
                    s1 = fmaf(fmaxf(d[mt][nt][3], 0.f), wv.y, s1);
                }
                s0 += __shfl_xor_sync(0xFFFFFFFF, s0, 1);
                s0 += __shfl_xor_sync(0xFFFFFFFF, s0, 2);
                s1 += __shfl_xor_sync(0xFFFFFFFF, s1, 1);
                s1 += __shfl_xor_sync(0xFFFFFFFF, s1, 2);
                if (cq == 0) {
                    int r0 = base_row + mt * 16 + gq;
                    if (r0 < N) out[r0] = s0;
                    if (r0 + 8 < N) out[r0 + 8] = s1;
                }
            }
        }
    }
}

extern "C" void kernel_launch(void* const* d_in, const int* in_sizes, int n_in,
                              void* d_out, int out_size) {
    (void)in_sizes; (void)n_in;
    const float* x      = (const float*)d_in[0];
    const float* t      = (const float*)d_in[1];
    const float* tbl_s  = (const float*)d_in[2];
    const float* tbl_d  = (const float*)d_in[3];
    const float* w10    = (const float*)d_in[4];
    const float* w11    = (const float*)d_in[5];
    const float* w12    = (const float*)d_in[6];
    const float* w20    = (const float*)d_in[7];
    const float* w21    = (const float*)d_in[8];
    const float* w22    = (const float*)d_in[9];
    const float* alpha  = (const float*)d_in[10];
    float* out = (float*)d_out;

    int N = out_size;
    if (N <= 0) return;
    if (N > NMAX) N = NMAX;

    // RES[l] = floor(16 * b^l), identical double-precision expr as reference
    ResParams rp;
    double b = pow(2048.0 / 16.0, 1.0 / 15.0);
    for (int l = 0; l < NLEV; l++)
        rp.r[l] = (int)floor(16.0 * pow(b, (double)l));

    int blocksN = (N + 255) / 256;

    pack_x_kernel<<<blocksN, 256>>>(x, N);

    dim3 gridP(2048, 16);
    build_comb_kernel<<<gridP, 256>>>(t, tbl_s, tbl_d, rp);

    dim3 gridA(blocksN, 16);
    encode_kernel<<<gridA, 256>>>(N, rp);

    cudaFuncSetAttribute(mlp_kernel, cudaFuncAttributeMaxDynamicSharedMemorySize, BSMEM);
    int blocksB = (N + BTPB - 1) / BTPB;
    mlp_kernel<<<blocksB, BTPB, BSMEM>>>(w10, w11, w12, w20, w21, w22, alpha, out, N);
}

// round 14
// speedup vs baseline: 1.2928x; 1.2928x over previous
#include <cuda_runtime.h>
#include <cuda_bf16.h>
#include <math.h>
#include <stdint.h>

#define NLEV 16
#define TMASK ((1u << 19) - 1u)
#define PR1 2654435761u
#define PR2 805459861u
#define PR3 3674653429u
#define NMAX 2097152

// interleaved feature scratch: plane c in [0,32), point i: g_feat2[c*NMAX+i] = {hi_word, lo_word}
__device__ uint2 g_feat2[32ull * NMAX];
// combined per-level table: (static.xy, time-fused-dynamic.zw) = 16 levels x 512K float4 = 128 MB
__device__ float4 g_tbl_comb[(size_t)NLEV << 19];
// packed coordinates (x0,x1,x2,unused): 32 MB
__device__ float4 g_x4[NMAX];
// weight fragments in B-fragment order (5 layers x 16 KB), L1-resident during MLP
__device__ __align__(16) char g_wfrag[5 * 16384];

struct ResParams { int r[NLEV]; };

// ---------------- helpers ----------------
__device__ __forceinline__ void mma16816(float d[4], const uint32_t a[4], uint32_t b0, uint32_t b1) {
    asm volatile("mma.sync.aligned.m16n8k16.row.col.f32.bf16.bf16.f32 "
        "{%0,%1,%2,%3}, {%4,%5,%6,%7}, {%8,%9}, {%0,%1,%2,%3};"
        : "+f"(d[0]), "+f"(d[1]), "+f"(d[2]), "+f"(d[3])
        : "r"(a[0]), "r"(a[1]), "r"(a[2]), "r"(a[3]), "r"(b0), "r"(b1));
}

// fast hi/lo bf16x2 split
__device__ __forceinline__ void split2(float v0, float v1, uint32_t& hi, uint32_t& lo) {
    uint32_t h;
    asm("cvt.rn.bf16x2.f32 %0, %1, %2;" : "=r"(h) : "f"(v1), "f"(v0));
    float h0 = __uint_as_float(h << 16);
    float h1 = __uint_as_float(h & 0xFFFF0000u);
    float l0 = v0 - h0, l1 = v1 - h1;
    uint32_t l;
    asm("cvt.rn.bf16x2.f32 %0, %1, %2;" : "=r"(l) : "f"(l1), "f"(l0));
    hi = h; lo = l;
}

__device__ __forceinline__ float bf2sum(uint32_t hi, uint32_t lo, int idx) {
    uint32_t hb = idx == 0 ? (hi << 16) : (hi & 0xFFFF0000u);
    uint32_t lb = idx == 0 ? (lo << 16) : (lo & 0xFFFF0000u);
    return __uint_as_float(hb) + __uint_as_float(lb);
}

__device__ __forceinline__ float2 lerp2(float2 a, float2 b, float f) {
    float2 r;
    r.x = fmaf(f, b.x - a.x, a.x);
    r.y = fmaf(f, b.y - a.y, a.y);
    return r;
}
__device__ __forceinline__ float4 lerp4(float4 a, float4 b, float f) {
    float4 r;
    r.x = fmaf(f, b.x - a.x, a.x);
    r.y = fmaf(f, b.y - a.y, a.y);
    r.z = fmaf(f, b.z - a.z, a.z);
    r.w = fmaf(f, b.w - a.w, a.w);
    return r;
}

// ================= kernel X: pack coordinates into float4 =================
__global__ void __launch_bounds__(256)
pack_x_kernel(const float* __restrict__ x, int N) {
    const int i = blockIdx.x * 256 + threadIdx.x;
    if (i >= N) return;
    g_x4[i] = make_float4(x[3 * i], x[3 * i + 1], x[3 * i + 2], 0.f);
}

// ================= kernel W: rearrange weights into B-fragment order =================
// 320 warps: g = layer*64 + tile*2 + j
__global__ void __launch_bounds__(256)
build_wfrag_kernel(const float* __restrict__ w10, const float* __restrict__ w11,
                   const float* __restrict__ w12, const float* __restrict__ w20,
                   const float* __restrict__ w21) {
    const int gw = (blockIdx.x * 256 + threadIdx.x) >> 5;
    const int lane = threadIdx.x & 31;
    if (gw >= 320) return;
    const int layer = gw >> 6;
    const int rem = gw & 63;
    const int tile = rem >> 1;          // kt*8 + nt
    const int j = rem & 1;
    const int kt = tile >> 3;
    const int cq = lane & 3, gq = lane >> 2;
    const int k0 = kt * 16 + cq * 2 + j * 8;
    const int n = (tile & 7) * 8 + gq;
    const float* Ws[5] = { w10, w11, w12, w20, w21 };
    const float* W = Ws[layer];
    float v0 = __ldg(W + k0 * 64 + n);
    float v1 = __ldg(W + (k0 + 1) * 64 + n);
    uint32_t hi, lo;
    split2(v0, v1, hi, lo);
    char* base = g_wfrag + layer * 16384 + tile * 512 + lane * 16 + j * 4;
    *reinterpret_cast<uint32_t*>(base) = hi;
    *reinterpret_cast<uint32_t*>(base + 8) = lo;
}

// ================= kernel P: build combined table =================
__global__ void __launch_bounds__(256)
build_comb_kernel(const float* __restrict__ tptr,
                  const float* __restrict__ tbl_s,
                  const float* __restrict__ tbl_d, ResParams rp) {
    const int l = blockIdx.y;
    const unsigned j = blockIdx.x * 256 + threadIdx.x;
    const float tv = __ldg(tptr);
    const float p3 = tv * (float)rp.r[l];
    const float g3 = floorf(p3);
    const float f3 = p3 - g3;
    const unsigned i3 = (unsigned)(int)g3;
    const unsigned hw0 = (i3 * PR3) & TMASK;
    const unsigned hw1 = ((i3 + 1u) * PR3) & TMASK;
    const float2* ts = (const float2*)tbl_s + ((size_t)l << 19);
    const float2* td = (const float2*)tbl_d + ((size_t)l << 19);
    float2 s = __ldg(ts + j);
    float2 a = __ldg(td + (j ^ hw0));
    float2 b = __ldg(td + (j ^ hw1));
    float2 d = lerp2(a, b, f3);
    g_tbl_comb[((size_t)l << 19) + j] = make_float4(s.x, s.y, d.x, d.y);
}

// ================= kernel A: level-parallel encode on the combined table =================
__global__ void __launch_bounds__(256)
encode_kernel(int N, ResParams rp) {
    const int i = blockIdx.x * 256 + threadIdx.x;
    if (i >= N) return;
    const int l = blockIdx.y;
    const float4* tb = g_tbl_comb + ((size_t)l << 19);

    const float4 xi = __ldg(&g_x4[i]);
    const float fr = (float)rp.r[l];
    float p0 = xi.x * fr, p1 = xi.y * fr, p2 = xi.z * fr;
    float g0 = floorf(p0), g1 = floorf(p1), g2 = floorf(p2);
    float f0 = p0 - g0, f1 = p1 - g1, f2 = p2 - g2;
    unsigned i0 = (unsigned)(int)g0, i1 = (unsigned)(int)g1, i2 = (unsigned)(int)g2;
    unsigned hy0 = i1 * PR1, hy1 = hy0 + PR1;
    unsigned hz0 = i2 * PR2, hz1 = hz0 + PR2;
    unsigned hyz[4] = { hy0 ^ hz0, hy0 ^ hz1, hy1 ^ hz0, hy1 ^ hz1 };
    unsigned i0b = i0 + 1u;

    float4 vlo[4], vhi[4];
#pragma unroll
    for (int j = 0; j < 4; j++) {
        vlo[j] = __ldg(tb + ((i0  ^ hyz[j]) & TMASK));
        vhi[j] = __ldg(tb + ((i0b ^ hyz[j]) & TMASK));
    }
    float4 u0 = lerp4(vlo[0], vhi[0], f0);
    float4 u1 = lerp4(vlo[1], vhi[1], f0);
    float4 u2 = lerp4(vlo[2], vhi[2], f0);
    float4 u3 = lerp4(vlo[3], vhi[3], f0);
    float4 s0 = lerp4(u0, u2, f1);
    float4 s1 = lerp4(u1, u3, f1);
    float4 r  = lerp4(s0, s1, f2);

    uint32_t hs, ls, hd, ld;
    split2(r.x, r.y, hs, ls);
    split2(r.z, r.w, hd, ld);
    __stcs(&g_feat2[(size_t)l * NMAX + i], make_uint2(hs, ls));
    __stcs(&g_feat2[(size_t)(16 + l) * NMAX + i], make_uint2(hd, ld));
}

// ================= kernel B: 5-layer MLP, mt-fused, nt-halved, zero smem =================
// 128 threads/CTA, 4 warps x 32 rows. Weights read via __ldg from g_wfrag (L1-resident).
#define BTPB 128

__global__ void __launch_bounds__(BTPB, 3)
mlp_kernel(const float* __restrict__ w22,
           const float* __restrict__ alphap,
           float* __restrict__ out, int N) {
    const int tid = threadIdx.x;
    const int wid = tid >> 5;
    const int lane = tid & 31;
    const int gq = lane >> 2;   // quad row 0..7
    const int cq = lane & 3;    // quad col 0..3

    const float alpha = __ldg(alphap);
    const float beta = 1.f - alpha;
    const int base_row = blockIdx.x * BTPB + wid * 32;   // mt adds 16

    uint32_t ah[2][16], al[2][16];

    // ---- preload layer-0 activation fragments from g_feat2 ----
#pragma unroll
    for (int mt = 0; mt < 2; mt++)
#pragma unroll
        for (int kt = 0; kt < 4; kt++) {
            size_t p0 = (size_t)(kt * 8 + cq) * NMAX + base_row + mt * 16 + gq;
            uint2 a0 = __ldcs(&g_feat2[p0]);
            uint2 a1 = __ldcs(&g_feat2[p0 + 8]);
            uint2 a2 = __ldcs(&g_feat2[p0 + 4ull * NMAX]);
            uint2 a3 = __ldcs(&g_feat2[p0 + 4ull * NMAX + 8]);
            ah[mt][kt * 4 + 0] = a0.x; al[mt][kt * 4 + 0] = a0.y;
            ah[mt][kt * 4 + 1] = a1.x; al[mt][kt * 4 + 1] = a1.y;
            ah[mt][kt * 4 + 2] = a2.x; al[mt][kt * 4 + 2] = a2.y;
            ah[mt][kt * 4 + 3] = a3.x; al[mt][kt * 4 + 3] = a3.y;
        }

    float s[2][2] = { {0.f, 0.f}, {0.f, 0.f} };   // final-layer partial dots

#pragma unroll
    for (int layer = 0; layer < 5; layer++) {
        uint32_t nh[2][16], nl[2][16];

#pragma unroll
        for (int half = 0; half < 2; half++) {
            float d[2][4][4];
#pragma unroll
            for (int mt = 0; mt < 2; mt++)
#pragma unroll
                for (int ntl = 0; ntl < 4; ntl++)
#pragma unroll
                    for (int q = 0; q < 4; q++) d[mt][ntl][q] = 0.f;

#pragma unroll
            for (int kt = 0; kt < 4; kt++) {
#pragma unroll
                for (int ntl = 0; ntl < 4; ntl++) {
                    const int nt = half * 4 + ntl;
                    uint4 w = __ldg(reinterpret_cast<const uint4*>(
                        g_wfrag + layer * 16384 + (kt * 8 + nt) * 512 + lane * 16));
#pragma unroll
                    for (int mt = 0; mt < 2; mt++) {
                        mma16816(d[mt][ntl], &ah[mt][kt * 4], w.x, w.y);
                        mma16816(d[mt][ntl], &ah[mt][kt * 4], w.z, w.w);
                        mma16816(d[mt][ntl], &al[mt][kt * 4], w.x, w.y);
                    }
                }
            }

            if (layer < 4) {
#pragma unroll
                for (int mt = 0; mt < 2; mt++) {
#pragma unroll
                    for (int ntl = 0; ntl < 4; ntl++) {
                        const int nt = half * 4 + ntl;
#pragma unroll
                        for (int q = 0; q < 4; q++) d[mt][ntl][q] = fmaxf(d[mt][ntl][q], 0.f);
                        if (layer == 2) {
                            size_t pw = (size_t)(nt * 4 + cq) * NMAX + base_row + mt * 16 + gq;
                            uint2 fa = __ldcs(&g_feat2[pw]);
                            uint2 fb = __ldcs(&g_feat2[pw + 8]);
                            d[mt][ntl][0] = d[mt][ntl][0] * alpha + beta * bf2sum(fa.x, fa.y, 0);
                            d[mt][ntl][1] = d[mt][ntl][1] * alpha + beta * bf2sum(fa.x, fa.y, 1);
                            d[mt][ntl][2] = d[mt][ntl][2] * alpha + beta * bf2sum(fb.x, fb.y, 0);
                            d[mt][ntl][3] = d[mt][ntl][3] * alpha + beta * bf2sum(fb.x, fb.y, 1);
                        }
                    }
#pragma unroll
                    for (int kt2 = 0; kt2 < 2; kt2++) {
                        const int ktg = half * 2 + kt2;     // next-layer kt index
                        const int p = 2 * kt2;              // nt pair within this half
                        split2(d[mt][p][0],     d[mt][p][1],     nh[mt][ktg * 4 + 0], nl[mt][ktg * 4 + 0]);
                        split2(d[mt][p][2],     d[mt][p][3],     nh[mt][ktg * 4 + 1], nl[mt][ktg * 4 + 1]);
                        split2(d[mt][p + 1][0], d[mt][p + 1][1], nh[mt][ktg * 4 + 2], nl[mt][ktg * 4 + 2]);
                        split2(d[mt][p + 1][2], d[mt][p + 1][3], nh[mt][ktg * 4 + 3], nl[mt][ktg * 4 + 3]);
                    }
                }
            } else {
#pragma unroll
                for (int mt = 0; mt < 2; mt++)
#pragma unroll
                    for (int ntl = 0; ntl < 4; ntl++) {
                        const int nt = half * 4 + ntl;
                        float2 wv = __ldg(reinterpret_cast<const float2*>(w22 + nt * 8 + cq * 2));
                        s[mt][0] = fmaf(fmaxf(d[mt][ntl][0], 0.f), wv.x, s[mt][0]);
                        s[mt][0] = fmaf(fmaxf(d[mt][ntl][1], 0.f), wv.y, s[mt][0]);
                        s[mt][1] = fmaf(fmaxf(d[mt][ntl][2], 0.f), wv.x, s[mt][1]);
                        s[mt][1] = fmaf(fmaxf(d[mt][ntl][3], 0.f), wv.y, s[mt][1]);
                    }
            }
        }

        if (layer < 4) {
#pragma unroll
            for (int mt = 0; mt < 2; mt++)
#pragma unroll
                for (int q = 0; q < 16; q++) { ah[mt][q] = nh[mt][q]; al[mt][q] = nl[mt][q]; }
        }
    }

    // ---- final reduce & store ----
#pragma unroll
    for (int mt = 0; mt < 2; mt++) {
        float s0 = s[mt][0], s1 = s[mt][1];
        s0 += __shfl_xor_sync(0xFFFFFFFF, s0, 1);
        s0 += __shfl_xor_sync(0xFFFFFFFF, s0, 2);
        s1 += __shfl_xor_sync(0xFFFFFFFF, s1, 1);
        s1 += __shfl_xor_sync(0xFFFFFFFF, s1, 2);
        if (cq == 0) {
            int r0 = base_row + mt * 16 + gq;
            if (r0 < N) out[r0] = s0;
            if (r0 + 8 < N) out[r0 + 8] = s1;
        }
    }
}

extern "C" void kernel_launch(void* const* d_in, const int* in_sizes, int n_in,
                              void* d_out, int out_size) {
    (void)in_sizes; (void)n_in;
    const float* x      = (const float*)d_in[0];
    const float* t      = (const float*)d_in[1];
    const float* tbl_s  = (const float*)d_in[2];
    const float* tbl_d  = (const float*)d_in[3];
    const float* w10    = (const float*)d_in[4];
    const float* w11    = (const float*)d_in[5];
    const float* w12    = (const float*)d_in[6];
    const float* w20    = (const float*)d_in[7];
    const float* w21    = (const float*)d_in[8];
    const float* w22    = (const float*)d_in[9];
    const float* alpha  = (const float*)d_in[10];
    float* out = (float*)d_out;

    int N = out_size;
    if (N <= 0) return;
    if (N > NMAX) N = NMAX;

    ResParams rp;
    double b = pow(2048.0 / 16.0, 1.0 / 15.0);
    for (int l = 0; l < NLEV; l++)
        rp.r[l] = (int)floor(16.0 * pow(b, (double)l));

    int blocksN = (N + 255) / 256;

    pack_x_kernel<<<blocksN, 256>>>(x, N);
    build_wfrag_kernel<<<40, 256>>>(w10, w11, w12, w20, w21);

    dim3 gridP(2048, 16);
    build_comb_kernel<<<gridP, 256>>>(t, tbl_s, tbl_d, rp);

    dim3 gridA(blocksN, 16);
    encode_kernel<<<gridA, 256>>>(N, rp);

    int blocksB = (N + BTPB - 1) / BTPB;
    mlp_kernel<<<blocksB, BTPB>>>(w22, alpha, out, N);
}